// round 10
// baseline (speedup 1.0000x reference)
#include <cuda_runtime.h>
#include <math.h>
#include <float.h>

// Shapes (fixed): x [8,512,64,64] f32; w1 [32,512]; b1 [32]; w2 [512,32]; b2 [512]
#define NPLANES 4096
#define NPAIRS  (NPLANES / 2)
#define PLANE_ELEMS 4096
#define HW 64
#define NEG_INF (-FLT_MAX)

// row-max arrays in smem (per plane): stride 64, 6 pad rows top/bottom;
// rowB's top pad band is rowS's bottom pad band (both constant -inf).
#define RSTR 64
#define ROFF 6
#define ROWB_OFF   (70 * RSTR)
#define PLANE_SM   (70 * RSTR + 76 * RSTR)     // 9344 floats per plane
#define SMEM_FLOATS (2 * PLANE_SM)             // 18688 floats = 74752 B

#define POOL_GRID 444                           // 148 SMs * 3 CTAs

// Scratch (no allocations allowed -> device globals)
__device__ float g_gap[NPLANES];
__device__ int   g_q[NPLANES];
__device__ float g_fb[NPLANES];

// ---------------------------------------------------------------------------
// Kernel 1: per-plane mean
// ---------------------------------------------------------------------------
__global__ __launch_bounds__(256) void gap_kernel(const float* __restrict__ x) {
    const int plane = blockIdx.x;
    const float4* __restrict__ p =
        reinterpret_cast<const float4*>(x + (size_t)plane * PLANE_ELEMS);

    float sum = 0.f;
    #pragma unroll 4
    for (int i = threadIdx.x; i < PLANE_ELEMS / 4; i += 256) {
        float4 v = p[i];
        sum += (v.x + v.y) + (v.z + v.w);
    }
    #pragma unroll
    for (int off = 16; off > 0; off >>= 1)
        sum += __shfl_down_sync(0xffffffffu, sum, off);

    __shared__ float warp_sums[8];
    const int lane = threadIdx.x & 31, wid = threadIdx.x >> 5;
    if (lane == 0) warp_sums[wid] = sum;
    __syncthreads();
    if (threadIdx.x == 0) {
        float t = 0.f;
        #pragma unroll
        for (int i = 0; i < 8; i++) t += warp_sums[i];
        g_gap[plane] = t * (1.0f / (float)PLANE_ELEMS);
    }
}

// ---------------------------------------------------------------------------
// Kernel 2: SE bottleneck + routing
// ---------------------------------------------------------------------------
__global__ __launch_bounds__(512) void se_kernel(const float* __restrict__ w1,
                                                 const float* __restrict__ b1,
                                                 const float* __restrict__ w2,
                                                 const float* __restrict__ b2) {
    __shared__ float sgap[512];
    __shared__ float shmid[32];
    const int b = blockIdx.x;
    const int t = threadIdx.x;

    sgap[t] = g_gap[b * 512 + t];
    __syncthreads();

    if (t < 32) {
        float acc = b1[t];
        const float* wr = w1 + t * 512;
        #pragma unroll 8
        for (int k = 0; k < 512; k++) acc = fmaf(sgap[k], wr[k], acc);
        shmid[t] = fmaxf(acc, 0.f);
    }
    __syncthreads();

    float acc = b2[t];
    const float* wr = w2 + t * 32;
    #pragma unroll
    for (int j = 0; j < 32; j++) acc = fmaf(shmid[j], wr[j], acc);
    const float s = fmaxf(acc, 0.f);

    int q = (int)floorf(s);
    q = min(max(q, 0), 5);
    const int plane = b * 512 + t;
    g_q[plane]  = q;
    g_fb[plane] = s - (float)q;
}

// ---------------------------------------------------------------------------
__device__ __forceinline__ float4 fmax4(float4 a, float4 b) {
    return make_float4(fmaxf(a.x, b.x), fmaxf(a.y, b.y),
                       fmaxf(a.z, b.z), fmaxf(a.w, b.w));
}
__device__ __forceinline__ float4 ld4s(const float* p) {
    return *reinterpret_cast<const float4*>(p);
}

// 4 sliding maxes of window W over float4 rows in smem at stride RSTR floats.
template<int W>
__device__ __forceinline__ void colslide(const float* __restrict__ base,
                                         float4 out[4]) {
    if constexpr (W == 1) {
        #pragma unroll
        for (int j = 0; j < 4; j++) out[j] = ld4s(base + j * RSTR);
    } else if constexpr (W <= 3) {
        float4 a[W + 3];
        #pragma unroll
        for (int k = 0; k < W + 3; k++) a[k] = ld4s(base + k * RSTR);
        #pragma unroll
        for (int j = 0; j < 4; j++) {
            float4 m = a[j];
            #pragma unroll
            for (int u = 1; u < W; u++) m = fmax4(m, a[j + u]);
            out[j] = m;
        }
    } else {
        float4 a0 = ld4s(base), a1 = ld4s(base + RSTR), a2 = ld4s(base + 2 * RSTR);
        float4 core = ld4s(base + 3 * RSTR);
        #pragma unroll
        for (int k = 4; k < W; k++) core = fmax4(core, ld4s(base + k * RSTR));
        float4 aW  = ld4s(base + W * RSTR);
        float4 aW1 = ld4s(base + (W + 1) * RSTR);
        float4 aW2 = ld4s(base + (W + 2) * RSTR);
        out[0] = fmax4(fmax4(core, a0), fmax4(a1, a2));
        out[1] = fmax4(fmax4(core, a1), fmax4(a2, aW));
        out[2] = fmax4(fmax4(core, a2), fmax4(aW, aW1));
        out[3] = fmax4(fmax4(core, aW), fmax4(aW1, aW2));
    }
}

// ---------------------------------------------------------------------------
// Row pass for one plane: quads already in registers; shuffles for neighbor
// columns. Lane layout: lanes 0-15 = one row, 16-31 = next; c = lane & 15.
// ---------------------------------------------------------------------------
template<int R>
__device__ __forceinline__ void row_pass(const float4* __restrict__ q,
                                         float* __restrict__ rowS,
                                         float* __restrict__ rowB) {
    const int t = threadIdx.x;
    const int c = t & 15;
    const unsigned FULL = 0xffffffffu;

    #pragma unroll
    for (int k = 0; k < 4; k++) {
        const int i = t + (k << 8);
        const int y = i >> 4;

        float r[20];   // r[idx] = col 4c - 8 + idx; r[2..17] used (R<=5)
        r[8] = q[k].x; r[9] = q[k].y; r[10] = q[k].z; r[11] = q[k].w;
        r[4]  = __shfl_up_sync(FULL, q[k].x, 1);
        r[5]  = __shfl_up_sync(FULL, q[k].y, 1);
        r[6]  = __shfl_up_sync(FULL, q[k].z, 1);
        r[7]  = __shfl_up_sync(FULL, q[k].w, 1);
        r[2]  = __shfl_up_sync(FULL, q[k].z, 2);
        r[3]  = __shfl_up_sync(FULL, q[k].w, 2);
        r[12] = __shfl_down_sync(FULL, q[k].x, 1);
        r[13] = __shfl_down_sync(FULL, q[k].y, 1);
        r[14] = __shfl_down_sync(FULL, q[k].z, 1);
        r[15] = __shfl_down_sync(FULL, q[k].w, 1);
        r[16] = __shfl_down_sync(FULL, q[k].x, 2);
        r[17] = __shfl_down_sync(FULL, q[k].y, 2);
        if (c < 1)  { r[4] = r[5] = r[6] = r[7] = NEG_INF; }
        if (c < 2)  { r[2] = r[3] = NEG_INF; }
        if (c > 14) { r[12] = r[13] = r[14] = r[15] = NEG_INF; }
        if (c > 13) { r[16] = r[17] = NEG_INF; }

        float mS[4], mB[4];
        if constexpr (R == 0) {
            #pragma unroll
            for (int j = 0; j < 4; j++) mS[j] = r[8 + j];
        } else if constexpr (R == 1) {
            #pragma unroll
            for (int j = 0; j < 4; j++)
                mS[j] = fmaxf(r[7 + j], fmaxf(r[8 + j], r[9 + j]));
        } else {
            float core = r[11 - R];
            #pragma unroll
            for (int u = 12 - R; u <= 8 + R; u++) core = fmaxf(core, r[u]);
            mS[0] = fmaxf(fmaxf(core, r[8 - R]),  fmaxf(r[9 - R],  r[10 - R]));
            mS[1] = fmaxf(fmaxf(core, r[9 - R]),  fmaxf(r[10 - R], r[9 + R]));
            mS[2] = fmaxf(fmaxf(core, r[10 - R]), fmaxf(r[9 + R],  r[10 + R]));
            mS[3] = fmaxf(fmaxf(core, r[9 + R]),  fmaxf(r[10 + R], r[11 + R]));
        }
        #pragma unroll
        for (int j = 0; j < 4; j++)
            mB[j] = fmaxf(mS[j], fmaxf(r[7 - R + j], r[9 + R + j]));

        const int ro = (y + ROFF) * RSTR + (c << 2);
        *reinterpret_cast<float4*>(rowS + ro) = make_float4(mS[0], mS[1], mS[2], mS[3]);
        *reinterpret_cast<float4*>(rowB + ro) = make_float4(mB[0], mB[1], mB[2], mB[3]);
    }
}

// ---------------------------------------------------------------------------
// Column pass for one plane (after barrier): residual from gmem.
// ---------------------------------------------------------------------------
template<int R>
__device__ __forceinline__ void col_pass(const float* __restrict__ xg,
                                         float* __restrict__ outg,
                                         const float* __restrict__ rowS,
                                         const float* __restrict__ rowB,
                                         float fb) {
    const int t = threadIdx.x;
    const int c4 = (t & 15) << 2, y0 = (t >> 4) << 2;
    const float fs = 1.0f - fb;

    float4 res[4];
    #pragma unroll
    for (int j = 0; j < 4; j++)
        res[j] = *reinterpret_cast<const float4*>(xg + (y0 + j) * HW + c4);

    float4 part[4];
    {
        float4 mS4[4];
        colslide<2 * R + 1>(rowS + (y0 - R + ROFF) * RSTR + c4, mS4);
        #pragma unroll
        for (int j = 0; j < 4; j++) {
            part[j].x = fmaf(fs, mS4[j].x, res[j].x);
            part[j].y = fmaf(fs, mS4[j].y, res[j].y);
            part[j].z = fmaf(fs, mS4[j].z, res[j].z);
            part[j].w = fmaf(fs, mS4[j].w, res[j].w);
        }
    }
    {
        float4 mB4[4];
        colslide<2 * R + 3>(rowB + (y0 - R - 1 + ROFF) * RSTR + c4, mB4);
        #pragma unroll
        for (int j = 0; j < 4; j++) {
            float4 o;
            o.x = fmaf(fb, mB4[j].x, part[j].x);
            o.y = fmaf(fb, mB4[j].y, part[j].y);
            o.z = fmaf(fb, mB4[j].z, part[j].z);
            o.w = fmaf(fb, mB4[j].w, part[j].w);
            *reinterpret_cast<float4*>(outg + (y0 + j) * HW + c4) = o;
        }
    }
}

#define ROW_DISPATCH(rr, q, rs, rb)                      \
    switch (rr) {                                        \
        case 0: row_pass<0>(q, rs, rb); break;           \
        case 1: row_pass<1>(q, rs, rb); break;           \
        case 2: row_pass<2>(q, rs, rb); break;           \
        case 3: row_pass<3>(q, rs, rb); break;           \
        case 4: row_pass<4>(q, rs, rb); break;           \
        default: row_pass<5>(q, rs, rb); break;          \
    }

#define COL_DISPATCH(rr, xg, og, rs, rb, fb)             \
    switch (rr) {                                        \
        case 0: col_pass<0>(xg, og, rs, rb, fb); break;  \
        case 1: col_pass<1>(xg, og, rs, rb, fb); break;  \
        case 2: col_pass<2>(xg, og, rs, rb, fb); break;  \
        case 3: col_pass<3>(xg, og, rs, rb, fb); break;  \
        case 4: col_pass<4>(xg, og, rs, rb, fb); break;  \
        default: col_pass<5>(xg, og, rs, rb, fb); break; \
    }

// ---------------------------------------------------------------------------
// Kernel 3: persistent, TWO planes interleaved per iteration.
// 2 barriers per pair = 1 per plane; double independent work between barriers.
// ---------------------------------------------------------------------------
__global__ __launch_bounds__(256, 3) void pool_kernel(const float* __restrict__ x,
                                                      float* __restrict__ out) {
    extern __shared__ float smem[];
    float* rowSA = smem;
    float* rowBA = smem + ROWB_OFF;
    float* rowSB = smem + PLANE_SM;
    float* rowBB = smem + PLANE_SM + ROWB_OFF;
    const int t = threadIdx.x;

    // fill constant -inf pads once per block (both plane slots)
    for (int i = t; i < 18 * 64; i += 256) {
        const int r = i >> 6, cc = i & 63;
        int off;
        if (r < 6)       off = r * RSTR + cc;                     // rowS top
        else if (r < 12) off = ROWB_OFF + (r - 6) * RSTR + cc;    // shared band
        else             off = ROWB_OFF + (70 + r - 12) * RSTR + cc; // rowB bot
        smem[off] = NEG_INF;
        smem[PLANE_SM + off] = NEG_INF;
    }
    __syncthreads();

    for (int pair = blockIdx.x; pair < NPAIRS; pair += gridDim.x) {
        const int pA = pair << 1, pB = pA + 1;
        const float* xgA = x + (size_t)pA * PLANE_ELEMS;
        const float* xgB = x + (size_t)pB * PLANE_ELEMS;
        float* ogA = out + (size_t)pA * PLANE_ELEMS;
        float* ogB = out + (size_t)pB * PLANE_ELEMS;
        const int   rA = g_q[pA],  rB = g_q[pB];
        const float fA = g_fb[pA], fB = g_fb[pB];

        // batch ALL 8 row-pass loads (one exposed round trip per pair)
        float4 qA[4], qB[4];
        #pragma unroll
        for (int k = 0; k < 4; k++) {
            qA[k] = *reinterpret_cast<const float4*>(xgA + ((t + (k << 8)) << 2));
            qB[k] = *reinterpret_cast<const float4*>(xgB + ((t + (k << 8)) << 2));
        }

        ROW_DISPATCH(rA, qA, rowSA, rowBA);
        ROW_DISPATCH(rB, qB, rowSB, rowBB);
        __syncthreads();   // both planes' row maxes ready

        COL_DISPATCH(rA, xgA, ogA, rowSA, rowBA, fA);
        COL_DISPATCH(rB, xgB, ogB, rowSB, rowBB, fB);
        __syncthreads();   // smem consumed; safe to overwrite next iteration
    }
}

// ---------------------------------------------------------------------------
extern "C" void kernel_launch(void* const* d_in, const int* in_sizes, int n_in,
                              void* d_out, int out_size) {
    const float* x  = (const float*)d_in[0];
    const float* w1 = (const float*)d_in[1];
    const float* b1 = (const float*)d_in[2];
    const float* w2 = (const float*)d_in[3];
    const float* b2 = (const float*)d_in[4];
    float* out = (float*)d_out;

    const int smem_bytes = SMEM_FLOATS * (int)sizeof(float);   // 74752
    cudaFuncSetAttribute(pool_kernel,
                         cudaFuncAttributeMaxDynamicSharedMemorySize, smem_bytes);

    gap_kernel<<<NPLANES, 256>>>(x);
    se_kernel<<<8, 512>>>(w1, b1, w2, b2);
    pool_kernel<<<POOL_GRID, 256, smem_bytes>>>(x, out);
}

// round 11
// speedup vs baseline: 1.0249x; 1.0249x over previous
#include <cuda_runtime.h>
#include <math.h>
#include <float.h>

// Shapes (fixed): x [8,512,64,64] f32; w1 [32,512]; b1 [32]; w2 [512,32]; b2 [512]
#define NPLANES 4096
#define PLANE_ELEMS 4096
#define HW 64
#define NEG_INF (-FLT_MAX)

// Per-CTA smem: rowS/rowB for 44 srows (6 halo+pad each side of 32 output
// rows), stride 64. srow s corresponds to global row (s - 6 + y0).
#define RSTR 64
#define NSROW 44

// Scratch (no allocations allowed -> device globals)
__device__ float g_gap[NPLANES];
__device__ int   g_q[NPLANES];
__device__ float g_fb[NPLANES];

// ---------------------------------------------------------------------------
// Kernel 1: per-plane mean
// ---------------------------------------------------------------------------
__global__ __launch_bounds__(256) void gap_kernel(const float* __restrict__ x) {
    const int plane = blockIdx.x;
    const float4* __restrict__ p =
        reinterpret_cast<const float4*>(x + (size_t)plane * PLANE_ELEMS);

    float sum = 0.f;
    #pragma unroll 4
    for (int i = threadIdx.x; i < PLANE_ELEMS / 4; i += 256) {
        float4 v = p[i];
        sum += (v.x + v.y) + (v.z + v.w);
    }
    #pragma unroll
    for (int off = 16; off > 0; off >>= 1)
        sum += __shfl_down_sync(0xffffffffu, sum, off);

    __shared__ float warp_sums[8];
    const int lane = threadIdx.x & 31, wid = threadIdx.x >> 5;
    if (lane == 0) warp_sums[wid] = sum;
    __syncthreads();
    if (threadIdx.x == 0) {
        float t = 0.f;
        #pragma unroll
        for (int i = 0; i < 8; i++) t += warp_sums[i];
        g_gap[plane] = t * (1.0f / (float)PLANE_ELEMS);
    }
}

// ---------------------------------------------------------------------------
// Kernel 2: SE bottleneck + routing
// ---------------------------------------------------------------------------
__global__ __launch_bounds__(512) void se_kernel(const float* __restrict__ w1,
                                                 const float* __restrict__ b1,
                                                 const float* __restrict__ w2,
                                                 const float* __restrict__ b2) {
    __shared__ float sgap[512];
    __shared__ float shmid[32];
    const int b = blockIdx.x;
    const int t = threadIdx.x;

    sgap[t] = g_gap[b * 512 + t];
    __syncthreads();

    if (t < 32) {
        float acc = b1[t];
        const float* wr = w1 + t * 512;
        #pragma unroll 8
        for (int k = 0; k < 512; k++) acc = fmaf(sgap[k], wr[k], acc);
        shmid[t] = fmaxf(acc, 0.f);
    }
    __syncthreads();

    float acc = b2[t];
    const float* wr = w2 + t * 32;
    #pragma unroll
    for (int j = 0; j < 32; j++) acc = fmaf(shmid[j], wr[j], acc);
    const float s = fmaxf(acc, 0.f);

    int q = (int)floorf(s);
    q = min(max(q, 0), 5);
    const int plane = b * 512 + t;
    g_q[plane]  = q;
    g_fb[plane] = s - (float)q;
}

// ---------------------------------------------------------------------------
__device__ __forceinline__ float4 fmax4(float4 a, float4 b) {
    return make_float4(fmaxf(a.x, b.x), fmaxf(a.y, b.y),
                       fmaxf(a.z, b.z), fmaxf(a.w, b.w));
}
__device__ __forceinline__ float4 ld4s(const float* p) {
    return *reinterpret_cast<const float4*>(p);
}

// 4 sliding maxes of window W over float4 rows in smem at stride RSTR.
template<int W>
__device__ __forceinline__ void colslide(const float* __restrict__ base,
                                         float4 out[4]) {
    if constexpr (W == 1) {
        #pragma unroll
        for (int j = 0; j < 4; j++) out[j] = ld4s(base + j * RSTR);
    } else if constexpr (W <= 3) {
        float4 a[W + 3];
        #pragma unroll
        for (int k = 0; k < W + 3; k++) a[k] = ld4s(base + k * RSTR);
        #pragma unroll
        for (int j = 0; j < 4; j++) {
            float4 m = a[j];
            #pragma unroll
            for (int u = 1; u < W; u++) m = fmax4(m, a[j + u]);
            out[j] = m;
        }
    } else {
        float4 a0 = ld4s(base), a1 = ld4s(base + RSTR), a2 = ld4s(base + 2 * RSTR);
        float4 core = ld4s(base + 3 * RSTR);
        #pragma unroll
        for (int k = 4; k < W; k++) core = fmax4(core, ld4s(base + k * RSTR));
        float4 aW  = ld4s(base + W * RSTR);
        float4 aW1 = ld4s(base + (W + 1) * RSTR);
        float4 aW2 = ld4s(base + (W + 2) * RSTR);
        out[0] = fmax4(fmax4(core, a0), fmax4(a1, a2));
        out[1] = fmax4(fmax4(core, a1), fmax4(a2, aW));
        out[2] = fmax4(fmax4(core, a2), fmax4(aW, aW1));
        out[3] = fmax4(fmax4(core, aW), fmax4(aW1, aW2));
    }
}

// ---------------------------------------------------------------------------
// Row pass over 38 real rows (608 quads, 5 iterations of 128 threads; the
// final partial iteration drops exactly one whole warp, so shuffles stay
// full-warp). Lanes 0-15 = one row, 16-31 = next row; c = lane & 15.
// ---------------------------------------------------------------------------
template<int R>
__device__ __forceinline__ void row_pass(const float4* __restrict__ q,
                                         float* __restrict__ rowS,
                                         float* __restrict__ rowB,
                                         int rs0) {
    const int t = threadIdx.x;
    const int c = t & 15;
    const unsigned FULL = 0xffffffffu;

    #pragma unroll
    for (int k = 0; k < 5; k++) {
        const int idx = t + (k << 7);
        if (idx < 608) {                       // warp-uniform guard
            float r[20];  // r[i] = col 4c - 8 + i; r[2..17] used (R<=5)
            r[8] = q[k].x; r[9] = q[k].y; r[10] = q[k].z; r[11] = q[k].w;
            r[4]  = __shfl_up_sync(FULL, q[k].x, 1);
            r[5]  = __shfl_up_sync(FULL, q[k].y, 1);
            r[6]  = __shfl_up_sync(FULL, q[k].z, 1);
            r[7]  = __shfl_up_sync(FULL, q[k].w, 1);
            r[2]  = __shfl_up_sync(FULL, q[k].z, 2);
            r[3]  = __shfl_up_sync(FULL, q[k].w, 2);
            r[12] = __shfl_down_sync(FULL, q[k].x, 1);
            r[13] = __shfl_down_sync(FULL, q[k].y, 1);
            r[14] = __shfl_down_sync(FULL, q[k].z, 1);
            r[15] = __shfl_down_sync(FULL, q[k].w, 1);
            r[16] = __shfl_down_sync(FULL, q[k].x, 2);
            r[17] = __shfl_down_sync(FULL, q[k].y, 2);
            if (c < 1)  { r[4] = r[5] = r[6] = r[7] = NEG_INF; }
            if (c < 2)  { r[2] = r[3] = NEG_INF; }
            if (c > 14) { r[12] = r[13] = r[14] = r[15] = NEG_INF; }
            if (c > 13) { r[16] = r[17] = NEG_INF; }

            float mS[4], mB[4];
            if constexpr (R == 0) {
                #pragma unroll
                for (int j = 0; j < 4; j++) mS[j] = r[8 + j];
            } else if constexpr (R == 1) {
                #pragma unroll
                for (int j = 0; j < 4; j++)
                    mS[j] = fmaxf(r[7 + j], fmaxf(r[8 + j], r[9 + j]));
            } else {
                float core = r[11 - R];
                #pragma unroll
                for (int u = 12 - R; u <= 8 + R; u++) core = fmaxf(core, r[u]);
                mS[0] = fmaxf(fmaxf(core, r[8 - R]),  fmaxf(r[9 - R],  r[10 - R]));
                mS[1] = fmaxf(fmaxf(core, r[9 - R]),  fmaxf(r[10 - R], r[9 + R]));
                mS[2] = fmaxf(fmaxf(core, r[10 - R]), fmaxf(r[9 + R],  r[10 + R]));
                mS[3] = fmaxf(fmaxf(core, r[9 + R]),  fmaxf(r[10 + R], r[11 + R]));
            }
            #pragma unroll
            for (int j = 0; j < 4; j++)
                mB[j] = fmaxf(mS[j], fmaxf(r[7 - R + j], r[9 + R + j]));

            const int srow = rs0 + (idx >> 4);
            const int ro = srow * RSTR + (c << 2);
            *reinterpret_cast<float4*>(rowS + ro) =
                make_float4(mS[0], mS[1], mS[2], mS[3]);
            *reinterpret_cast<float4*>(rowB + ro) =
                make_float4(mB[0], mB[1], mB[2], mB[3]);
        }
    }
}

// ---------------------------------------------------------------------------
// Column pass for this CTA's 32 output rows (after barrier).
// Output local row y ∈ [0,32): mS over srows (y-R+6..y+R+6) ⊂ [1,42],
// mB over srows (y-R-1+6..y+R+1+6) ⊂ [0,43].
// ---------------------------------------------------------------------------
template<int R>
__device__ __forceinline__ void col_pass(const float* __restrict__ xg,
                                         float* __restrict__ outg,
                                         const float* __restrict__ rowS,
                                         const float* __restrict__ rowB,
                                         float fb, int y0) {
    const int t = threadIdx.x;
    const int c4 = (t & 15) << 2;
    const int yl = (t >> 4) << 2;              // 0,4,...,28
    const float fs = 1.0f - fb;

    float4 part[4];
    {
        float4 mS4[4];
        colslide<2 * R + 1>(rowS + (yl - R + 6) * RSTR + c4, mS4);
        // residual loads AFTER stage-S window regs die (keeps pressure low)
        #pragma unroll
        for (int j = 0; j < 4; j++) {
            const float4 res = *reinterpret_cast<const float4*>(
                xg + (y0 + yl + j) * HW + c4);
            part[j].x = fmaf(fs, mS4[j].x, res.x);
            part[j].y = fmaf(fs, mS4[j].y, res.y);
            part[j].z = fmaf(fs, mS4[j].z, res.z);
            part[j].w = fmaf(fs, mS4[j].w, res.w);
        }
    }
    {
        float4 mB4[4];
        colslide<2 * R + 3>(rowB + (yl - R - 1 + 6) * RSTR + c4, mB4);
        #pragma unroll
        for (int j = 0; j < 4; j++) {
            float4 o;
            o.x = fmaf(fb, mB4[j].x, part[j].x);
            o.y = fmaf(fb, mB4[j].y, part[j].y);
            o.z = fmaf(fb, mB4[j].z, part[j].z);
            o.w = fmaf(fb, mB4[j].w, part[j].w);
            *reinterpret_cast<float4*>(outg + (y0 + yl + j) * HW + c4) = o;
        }
    }
}

// ---------------------------------------------------------------------------
// Kernel 3: one CTA (128 threads) per half-plane. Non-persistent, grid 8192,
// ONE barrier per CTA, 22.5 KB smem -> 9 CTAs/SM.
// ---------------------------------------------------------------------------
__global__ __launch_bounds__(128, 9) void pool_kernel(const float* __restrict__ x,
                                                      float* __restrict__ out) {
    __shared__ float rowS[NSROW * RSTR];
    __shared__ float rowB[NSROW * RSTR];

    const int t = threadIdx.x;
    const int plane = blockIdx.x >> 1;
    const int half  = blockIdx.x & 1;
    const int y0    = half ? 32 : 0;   // first output row
    const int grow0 = half ? 26 : 0;   // first loaded input row
    const int rs0   = half ? 0  : 6;   // srow of first real row
    const int pad0  = half ? 38 : 0;   // first pad srow

    const float* xg = x + (size_t)plane * PLANE_ELEMS;
    float* outg = out + (size_t)plane * PLANE_ELEMS;
    const int   r  = g_q[plane];
    const float fb = g_fb[plane];

    // fill 6 pad srows of each array with -inf
    #pragma unroll
    for (int i = t; i < 12 * 64; i += 128) {
        const int pr = i >> 6, cc = i & 63;
        if (pr < 6) rowS[(pad0 + pr) * RSTR + cc] = NEG_INF;
        else        rowB[(pad0 + pr - 6) * RSTR + cc] = NEG_INF;
    }

    // batch all row-pass loads (38 rows x 16 quads = 608 items, 5 iters)
    float4 q[5];
    #pragma unroll
    for (int k = 0; k < 5; k++) {
        const int idx = t + (k << 7);
        if (idx < 608) {
            const int gr = grow0 + (idx >> 4);
            q[k] = *reinterpret_cast<const float4*>(
                xg + gr * HW + ((idx & 15) << 2));
        }
    }

    switch (r) {
        case 0: row_pass<0>(q, rowS, rowB, rs0); __syncthreads();
                col_pass<0>(xg, outg, rowS, rowB, fb, y0); break;
        case 1: row_pass<1>(q, rowS, rowB, rs0); __syncthreads();
                col_pass<1>(xg, outg, rowS, rowB, fb, y0); break;
        case 2: row_pass<2>(q, rowS, rowB, rs0); __syncthreads();
                col_pass<2>(xg, outg, rowS, rowB, fb, y0); break;
        case 3: row_pass<3>(q, rowS, rowB, rs0); __syncthreads();
                col_pass<3>(xg, outg, rowS, rowB, fb, y0); break;
        case 4: row_pass<4>(q, rowS, rowB, rs0); __syncthreads();
                col_pass<4>(xg, outg, rowS, rowB, fb, y0); break;
        default: row_pass<5>(q, rowS, rowB, rs0); __syncthreads();
                col_pass<5>(xg, outg, rowS, rowB, fb, y0); break;
    }
}

// ---------------------------------------------------------------------------
extern "C" void kernel_launch(void* const* d_in, const int* in_sizes, int n_in,
                              void* d_out, int out_size) {
    const float* x  = (const float*)d_in[0];
    const float* w1 = (const float*)d_in[1];
    const float* b1 = (const float*)d_in[2];
    const float* w2 = (const float*)d_in[3];
    const float* b2 = (const float*)d_in[4];
    float* out = (float*)d_out;

    gap_kernel<<<NPLANES, 256>>>(x);
    se_kernel<<<8, 512>>>(w1, b1, w2, b2);
    pool_kernel<<<NPLANES * 2, 128>>>(x, out);
}